// round 4
// baseline (speedup 1.0000x reference)
#include <cuda_runtime.h>
#include <cuda_bf16.h>
#include <mma.h>
#include <cstdint>

using namespace nvcuda;

#define NN 100000
#define NE 600000

// ---------------- scratch (device globals; zero-init, no allocation allowed) ----------------
__device__ float g_a  [(size_t)(NN + 64) * 128];
__device__ float g_b  [(size_t)(NN + 64) * 128];
__device__ float g_p  [(size_t)(NN + 64) * 128];
__device__ float g_deg[NN];
__device__ __nv_bfloat16 g_wb[229376];      // 8 weight matrices, transposed, hi+lo
__device__ float g_bt[6 * 16 * 256];        // 6 bias tiles, 16 rows x 256, ld 256

// weight scratch offsets (elements): hi at off, lo at off + 128*ncols
// self0:0 neigh0:32768 fc:65536 fc2:98304 self1:131072 neigh1:163840 self2:196608 neigh2:212992

// split fp32 pair -> (hi bf16x2, lo bf16x2)
__device__ __forceinline__ void split2(float a, float b, uint32_t& hi, uint32_t& lo) {
    __nv_bfloat16 ha = __float2bfloat16(a), hb = __float2bfloat16(b);
    float ra = a - __bfloat162float(ha), rb = b - __bfloat162float(hb);
    __nv_bfloat16 la = __float2bfloat16(ra), lb = __float2bfloat16(rb);
    hi = ((uint32_t)__bfloat16_as_ushort(hb) << 16) | (uint32_t)__bfloat16_as_ushort(ha);
    lo = ((uint32_t)__bfloat16_as_ushort(lb) << 16) | (uint32_t)__bfloat16_as_ushort(la);
}

// ---------------- weight conversion: W[k][n] f32 -> transposed bf16 hi/lo [n*128+k] ----------------
struct WSrc { const float* s[8]; };

__global__ void wconv_k(WSrc ws) {
    int idx = blockIdx.x * blockDim.x + threadIdx.x;
    if (idx >= 114688) return;
    int m, r, ncols;
    if (idx < 98304) { m = idx >> 14; r = idx & 16383; ncols = 128; }
    else             { m = 6 + ((idx - 98304) >> 13); r = (idx - 98304) & 8191; ncols = 64; }
    const int offs[8] = {0, 32768, 65536, 98304, 131072, 163840, 196608, 212992};
    int k = r / ncols, n = r % ncols;
    float v = ws.s[m][r];
    __nv_bfloat16 h = __float2bfloat16(v);
    __nv_bfloat16 l = __float2bfloat16(v - __bfloat162float(h));
    int base = offs[m];
    g_wb[base + n * 128 + k]                = h;
    g_wb[base + 128 * ncols + n * 128 + k]  = l;
}

// ---------------- bias tiles: t in 0..5, 16 rows x 256 (rows identical) ----------------
__global__ void btile_k(const float* b0, const float* bfc, const float* bfc2,
                        const float* b1, const float* b2) {
    int idx = blockIdx.x * blockDim.x + threadIdx.x;
    if (idx >= 6 * 4096) return;
    int t = idx >> 12, c = idx & 255;
    float v = 0.f;
    if      (t == 0) { if (c < 128) v = b0[c]; }
    else if (t == 1) { if (c < 128) v = bfc[c]; }
    else if (t == 2) { if (c < 128) v = bfc2[c]; }
    else if (t == 3) { if (c < 128) v = b1[c]; }
    else if (t == 4) { if (c < 64)  v = b2[c]; }
    g_bt[idx] = v;
}

// ---------------- GEMM: [C1|C2][M,128] = [relu-in](A)[M,128] @ [W1|W2] + biastile ----
// 64-row CTA, 256 threads, 8 warps (2 row-groups x 4 col-groups), warp tile 32x32.
// A hi/lo in smem; B frags straight from preconverted global bf16; bias via acc init;
// direct fragment stores (scratch outputs oversized; MSK kernel masks C1 tail).
template<int BN1, int BN2, bool RIN, bool MSK>
__global__ __launch_bounds__(256, 2)
void mm2_k(const float* __restrict__ A,
           const __nv_bfloat16* __restrict__ w1hi, const __nv_bfloat16* __restrict__ w1lo,
           const __nv_bfloat16* __restrict__ w2hi, const __nv_bfloat16* __restrict__ w2lo,
           const float* __restrict__ bt, float* __restrict__ C1, float* __restrict__ C2, int M)
{
    constexpr int P = 136;
    __shared__ __nv_bfloat16 sA[2][64 * P];     // 34816 B

    const int tid = threadIdx.x;
    const int wid = tid >> 5;
    const int wr  = wid & 1;        // row group: rows wr*32
    const int wc  = wid >> 1;       // col group: cols wc*32
    const int m0  = blockIdx.x * 64;

    // ---- A tile: f32 coalesced float4 load, optional relu, hi/lo split ----
#pragma unroll
    for (int i = 0; i < 8; ++i) {
        int idx = tid + i * 256;          // 2048 float4s
        int m   = idx >> 5;
        int k0  = (idx & 31) * 4;
        float4 v = make_float4(0.f, 0.f, 0.f, 0.f);
        int gm = m0 + m;
        if (gm < M) v = *reinterpret_cast<const float4*>(A + (size_t)gm * 128 + k0);
        if (RIN) { v.x = fmaxf(v.x, 0.f); v.y = fmaxf(v.y, 0.f); v.z = fmaxf(v.z, 0.f); v.w = fmaxf(v.w, 0.f); }
        uint32_t h0, l0, h1, l1;
        split2(v.x, v.y, h0, l0);
        split2(v.z, v.w, h1, l1);
        *reinterpret_cast<uint2*>(&sA[0][m * P + k0]) = make_uint2(h0, h1);
        *reinterpret_cast<uint2*>(&sA[1][m * P + k0]) = make_uint2(l0, l1);
    }
    __syncthreads();

    const int  gc0  = wc * 32;
    const bool mat2 = (BN2 > 0) && (gc0 >= BN1);
    const __nv_bfloat16* whi = mat2 ? w2hi : w1hi;
    const __nv_bfloat16* wlo = mat2 ? w2lo : w1lo;
    const int  n0   = mat2 ? gc0 - BN1 : gc0;

    // ---- acc init = bias tile (broadcast rows) ----
    wmma::fragment<wmma::accumulator, 16, 16, 16, float> acc[2][2];
#pragma unroll
    for (int i = 0; i < 2; ++i)
#pragma unroll
        for (int j = 0; j < 2; ++j)
            wmma::load_matrix_sync(acc[i][j], bt + gc0 + j * 16, 256, wmma::mem_row_major);

    // ---- mainloop: 8 k-steps, 3-term bf16 split product ----
#pragma unroll
    for (int ks = 0; ks < 8; ++ks) {
        const int k = ks * 16;
        wmma::fragment<wmma::matrix_a, 16, 16, 16, __nv_bfloat16, wmma::row_major> ah[2], al[2];
        wmma::fragment<wmma::matrix_b, 16, 16, 16, __nv_bfloat16, wmma::col_major> bh[2], bl[2];
#pragma unroll
        for (int i = 0; i < 2; ++i) {
            int m = wr * 32 + i * 16;
            wmma::load_matrix_sync(ah[i], &sA[0][m * P + k], P);
            wmma::load_matrix_sync(al[i], &sA[1][m * P + k], P);
        }
#pragma unroll
        for (int j = 0; j < 2; ++j) {
            int n = n0 + j * 16;
            wmma::load_matrix_sync(bh[j], whi + (size_t)n * 128 + k, 128);
            wmma::load_matrix_sync(bl[j], wlo + (size_t)n * 128 + k, 128);
        }
#pragma unroll
        for (int i = 0; i < 2; ++i)
#pragma unroll
            for (int j = 0; j < 2; ++j) {
                wmma::mma_sync(acc[i][j], ah[i], bh[j], acc[i][j]);
                wmma::mma_sync(acc[i][j], ah[i], bl[j], acc[i][j]);
                wmma::mma_sync(acc[i][j], al[i], bh[j], acc[i][j]);
            }
    }

    // ---- epilogue ----
    float*    Cp  = mat2 ? C2 : C1;
    const int ldc = mat2 ? BN2 : BN1;
    const bool tail = MSK && (m0 + 64 > M);

    if (!tail) {
#pragma unroll
        for (int i = 0; i < 2; ++i) {
            int gm = m0 + wr * 32 + i * 16;
#pragma unroll
            for (int j = 0; j < 2; ++j)
                wmma::store_matrix_sync(Cp + (size_t)gm * ldc + n0 + j * 16, acc[i][j], ldc, wmma::mem_row_major);
        }
    } else {
        // tail CTA of the masked kernel: C2 direct (oversized scratch), C1 via masked smem staging
        if (mat2) {
#pragma unroll
            for (int i = 0; i < 2; ++i) {
                int gm = m0 + wr * 32 + i * 16;
#pragma unroll
                for (int j = 0; j < 2; ++j)
                    wmma::store_matrix_sync(Cp + (size_t)gm * ldc + n0 + j * 16, acc[i][j], ldc, wmma::mem_row_major);
            }
        }
        __syncthreads();                      // smem A no longer needed
        float* Cs = reinterpret_cast<float*>(sA);   // 64 x 68 staging (BN1 <= 64)
        if (!mat2) {
#pragma unroll
            for (int i = 0; i < 2; ++i)
#pragma unroll
                for (int j = 0; j < 2; ++j)
                    wmma::store_matrix_sync(&Cs[(wr * 32 + i * 16) * 68 + gc0 + j * 16], acc[i][j], 68, wmma::mem_row_major);
        }
        __syncthreads();
#pragma unroll
        for (int i = 0; i < 4; ++i) {         // 64 rows x 16 f4
            int idx = tid + i * 256;
            int r = idx >> 4, c = (idx & 15) * 4;
            if (m0 + r < M)
                *reinterpret_cast<float4*>(C1 + (size_t)(m0 + r) * BN1 + c) =
                    *reinterpret_cast<const float4*>(&Cs[r * 68 + c]);
        }
    }
}

// ---------------- graph kernels ----------------
__global__ void zero_k(float4* __restrict__ p, int n4) {
    int i = blockIdx.x * blockDim.x + threadIdx.x;
    if (i < n4) p[i] = make_float4(0.f, 0.f, 0.f, 0.f);
}

__global__ void deg_k(const int* __restrict__ dst) {
    int e = blockIdx.x * blockDim.x + threadIdx.x;
    if (e < NE) atomicAdd(&g_deg[dst[e]], 1.0f);
}

__global__ void inv_k() {
    int i = blockIdx.x * blockDim.x + threadIdx.x;
    if (i < NN) g_deg[i] = 1.0f / fmaxf(g_deg[i], 1.0f);
}

__device__ __forceinline__ void red4(float* p, float4 v) {
    asm volatile("red.global.add.v4.f32 [%0], {%1, %2, %3, %4};"
                 :: "l"(p), "f"(v.x), "f"(v.y), "f"(v.z), "f"(v.w) : "memory");
}

// out[dst[e]] += p[src[e]] * invdeg[dst[e]]   (out pre-initialized with self term + bias)
template<int DW>
__global__ void scatter_k(const float* __restrict__ p, const int* __restrict__ src,
                          const int* __restrict__ dst, float* __restrict__ out) {
    const int PV = DW / 4;
    int t = blockIdx.x * blockDim.x + threadIdx.x;
    int e = t / PV;
    if (e >= NE) return;
    int c = (t % PV) * 4;
    int sn = src[e];
    int dn = dst[e];
    float inv = g_deg[dn];
    float4 v = *reinterpret_cast<const float4*>(p + (size_t)sn * DW + c);
    v.x *= inv; v.y *= inv; v.z *= inv; v.w *= inv;
    red4(out + (size_t)dn * DW + c, v);
}

// ---------------- launch ----------------
extern "C" void kernel_launch(void* const* d_in, const int* in_sizes, int n_in,
                              void* d_out, int out_size) {
    const float* x        = (const float*)d_in[0];
    const int*   src      = (const int*)  d_in[1];
    const int*   dst      = (const int*)  d_in[2];
    const float* w_self0  = (const float*)d_in[3];
    const float* b_self0  = (const float*)d_in[4];
    const float* w_neigh0 = (const float*)d_in[5];
    const float* fc_w     = (const float*)d_in[6];
    const float* fc_b     = (const float*)d_in[7];
    const float* fc2_w    = (const float*)d_in[8];
    const float* fc2_b    = (const float*)d_in[9];
    const float* w_self1  = (const float*)d_in[10];
    const float* b_self1  = (const float*)d_in[11];
    const float* w_neigh1 = (const float*)d_in[12];
    const float* w_self2  = (const float*)d_in[13];
    const float* b_self2  = (const float*)d_in[14];
    const float* w_neigh2 = (const float*)d_in[15];
    float* out = (float*)d_out;

    float *p_a, *p_b, *p_p, *p_deg, *p_bt;
    __nv_bfloat16* p_wb;
    cudaGetSymbolAddress((void**)&p_a,   g_a);
    cudaGetSymbolAddress((void**)&p_b,   g_b);
    cudaGetSymbolAddress((void**)&p_p,   g_p);
    cudaGetSymbolAddress((void**)&p_deg, g_deg);
    cudaGetSymbolAddress((void**)&p_wb,  g_wb);
    cudaGetSymbolAddress((void**)&p_bt,  g_bt);

    const __nv_bfloat16 *s0h = p_wb,          *s0l = p_wb + 16384;
    const __nv_bfloat16 *n0h = p_wb + 32768,  *n0l = p_wb + 49152;
    const __nv_bfloat16 *fch = p_wb + 65536,  *fcl = p_wb + 81920;
    const __nv_bfloat16 *f2h = p_wb + 98304,  *f2l = p_wb + 114688;
    const __nv_bfloat16 *s1h = p_wb + 131072, *s1l = p_wb + 147456;
    const __nv_bfloat16 *n1h = p_wb + 163840, *n1l = p_wb + 180224;
    const __nv_bfloat16 *s2h = p_wb + 196608, *s2l = p_wb + 204800;
    const __nv_bfloat16 *n2h = p_wb + 212992, *n2l = p_wb + 221184;
    const float *bt0 = p_bt, *bt1 = p_bt + 4096, *bt2 = p_bt + 8192,
                *bt3 = p_bt + 12288, *bt4 = p_bt + 16384, *btZ = p_bt + 20480;

    const int T  = 256;
    const int GB = (NN + 63) / 64;   // 1563

    // ---- prep: degrees, weight conversion, bias tiles ----
    zero_k<<<(NN / 4 + T - 1) / T, T>>>((float4*)p_deg, NN / 4);
    deg_k<<<(NE + T - 1) / T, T>>>(dst);
    inv_k<<<(NN + T - 1) / T, T>>>();
    WSrc ws; ws.s[0] = w_self0; ws.s[1] = w_neigh0; ws.s[2] = fc_w; ws.s[3] = fc2_w;
             ws.s[4] = w_self1; ws.s[5] = w_neigh1; ws.s[6] = w_self2; ws.s[7] = w_neigh2;
    wconv_k<<<(114688 + T - 1) / T, T>>>(ws);
    btile_k<<<(6 * 4096 + T - 1) / T, T>>>(b_self0, fc_b, fc2_b, b_self1, b_self2);

    // ---- layer 0: NGNN SAGEConv (relu fused into consumers' A-load) ----
    mm2_k<128, 0, false, false><<<GB, T>>>(x, s0h, s0l, nullptr, nullptr, bt0, p_a, nullptr, NN);
    mm2_k<128, 0, false, false><<<GB, T>>>(x, n0h, n0l, nullptr, nullptr, btZ, p_p, nullptr, NN);
    scatter_k<128><<<(NE * 32 + T - 1) / T, T>>>(p_p, src, dst, p_a);      // p_a = conv0 (pre-relu)
    mm2_k<128, 0, true, false><<<GB, T>>>(p_a, fch, fcl, nullptr, nullptr, bt1, p_b, nullptr, NN);
    mm2_k<128, 0, true, false><<<GB, T>>>(p_b, f2h, f2l, nullptr, nullptr, bt2, p_a, nullptr, NN);

    // ---- layer 1: SAGEConv ----
    mm2_k<128, 0, true, false><<<GB, T>>>(p_a, s1h, s1l, nullptr, nullptr, bt3, p_b, nullptr, NN);
    mm2_k<128, 0, true, false><<<GB, T>>>(p_a, n1h, n1l, nullptr, nullptr, btZ, p_p, nullptr, NN);
    scatter_k<128><<<(NE * 32 + T - 1) / T, T>>>(p_p, src, dst, p_b);      // p_b = conv1 (pre-relu)

    // ---- layer 2 (output): fused self(64->out) + neigh(64->p_p) ----
    mm2_k<64, 64, true, true><<<GB, T>>>(p_b, s2h, s2l, n2h, n2l, bt4, out, p_p, NN);
    scatter_k<64><<<(NE * 16 + T - 1) / T, T>>>(p_p, src, dst, out);
}

// round 5
// speedup vs baseline: 1.2157x; 1.2157x over previous
#include <cuda_runtime.h>
#include <cuda_bf16.h>
#include <mma.h>
#include <cstdint>

using namespace nvcuda;

#define NN 100000
#define NE 600000

// ---------------- scratch (device globals; no allocation allowed) ----------------
__device__ float g_a  [(size_t)NN * 128];
__device__ float g_b  [(size_t)NN * 128];
__device__ float g_p  [(size_t)NN * 128];
__device__ float g_deg[NN];
__device__ __nv_bfloat16 g_wb[229376];      // 8 weight matrices, transposed [n*128+k], hi+lo

// split fp32 pair -> (hi bf16x2, lo bf16x2)
__device__ __forceinline__ void split2(float a, float b, uint32_t& hi, uint32_t& lo) {
    __nv_bfloat16 ha = __float2bfloat16(a), hb = __float2bfloat16(b);
    float ra = a - __bfloat162float(ha), rb = b - __bfloat162float(hb);
    __nv_bfloat16 la = __float2bfloat16(ra), lb = __float2bfloat16(rb);
    hi = ((uint32_t)__bfloat16_as_ushort(hb) << 16) | (uint32_t)__bfloat16_as_ushort(ha);
    lo = ((uint32_t)__bfloat16_as_ushort(lb) << 16) | (uint32_t)__bfloat16_as_ushort(la);
}

// ---------------- weight conversion: W[k][n] f32 -> transposed bf16 hi/lo [n*128+k] ----------------
struct WSrc { const float* s[8]; };

__global__ void wconv_k(WSrc ws) {
    int idx = blockIdx.x * blockDim.x + threadIdx.x;
    if (idx >= 114688) return;
    int m, r, ncols;
    if (idx < 98304) { m = idx >> 14; r = idx & 16383; ncols = 128; }
    else             { m = 6 + ((idx - 98304) >> 13); r = (idx - 98304) & 8191; ncols = 64; }
    const int offs[8] = {0, 32768, 65536, 98304, 131072, 163840, 196608, 212992};
    int k = r / ncols, n = r % ncols;
    float v = ws.s[m][r];
    __nv_bfloat16 h = __float2bfloat16(v);
    __nv_bfloat16 l = __float2bfloat16(v - __bfloat162float(h));
    int base = offs[m];
    g_wb[base + n * 128 + k]                = h;
    g_wb[base + 128 * ncols + n * 128 + k]  = l;
}

// ---------------- WMMA bf16 GEMM: C[M,BN] = [relu-in](A)[M,128] @ W[128,BN] (+bias) ----
// CTA tile 128 x BN, 512 threads (16 warps, 4x4 grid), warp tile 32 x BN/4.
// 2-term bf16 split, fp32 accumulate: A@W ~= Ahi@Whi + Ahi@Wlo + Alo@Whi.
// W comes preconverted (bf16 hi/lo, transposed [n][k]) -> pure uint4 smem copy.
template<int BN, bool RIN, bool BIAS>
__global__ __launch_bounds__(512)
void mm_k(const float* __restrict__ A,
          const __nv_bfloat16* __restrict__ whi, const __nv_bfloat16* __restrict__ wlo,
          const float* __restrict__ bias, float* __restrict__ C, int M)
{
    extern __shared__ char dsm[];
    constexpr int P   = 136;              // bf16 pitch (pad 8): 272B rows, LDSM conflict-free
    constexpr int ASZ = 128 * P * 2;      // one A tile bytes
    constexpr int WSZ = BN  * P * 2;      // one W tile bytes
    constexpr int NC  = BN / 64;          // 16-col frags per warp (2 @128, 1 @64)
    constexpr int CP  = BN + 4;           // f32 epilogue pitch

    __nv_bfloat16* Ahi = reinterpret_cast<__nv_bfloat16*>(dsm);
    __nv_bfloat16* Alo = reinterpret_cast<__nv_bfloat16*>(dsm + ASZ);
    __nv_bfloat16* Whi = reinterpret_cast<__nv_bfloat16*>(dsm + 2 * ASZ);
    __nv_bfloat16* Wlo = reinterpret_cast<__nv_bfloat16*>(dsm + 2 * ASZ + WSZ);
    float*         Cs  = reinterpret_cast<float*>(dsm);

    const int tid = threadIdx.x;
    const int wid = tid >> 5;
    const int wr  = wid & 3;              // warp row 0..3 -> rows wr*32
    const int wc  = wid >> 2;             // warp col 0..3 -> cols wc*(BN/4)
    const int m0  = blockIdx.x * 128;

    // ---- A tile: f32 coalesced float4 load, optional relu, hi/lo split ----
#pragma unroll
    for (int i = 0; i < 8; ++i) {
        int idx = tid + i * 512;          // 4096 float4s
        int m   = idx >> 5;
        int k0  = (idx & 31) * 4;
        float4 v = make_float4(0.f, 0.f, 0.f, 0.f);
        int gm = m0 + m;
        if (gm < M) v = *reinterpret_cast<const float4*>(A + (size_t)gm * 128 + k0);
        if (RIN) { v.x = fmaxf(v.x, 0.f); v.y = fmaxf(v.y, 0.f); v.z = fmaxf(v.z, 0.f); v.w = fmaxf(v.w, 0.f); }
        uint32_t h0, l0, h1, l1;
        split2(v.x, v.y, h0, l0);
        split2(v.z, v.w, h1, l1);
        *reinterpret_cast<uint2*>(&Ahi[m * P + k0]) = make_uint2(h0, h1);
        *reinterpret_cast<uint2*>(&Alo[m * P + k0]) = make_uint2(l0, l1);
    }

    // ---- W tile: preconverted bf16, straight uint4 copy with repitch (128 -> P) ----
    constexpr int WU4 = BN * 16;          // uint4 per half (hi or lo)
#pragma unroll
    for (int i = 0; i < (2 * WU4) / 512; ++i) {
        int idx  = tid + i * 512;
        int half = idx / WU4;
        int r    = idx - half * WU4;
        int n    = r >> 4;
        int c    = r & 15;
        const uint4* srcp = reinterpret_cast<const uint4*>(half ? wlo : whi);
        __nv_bfloat16* dp = half ? Wlo : Whi;
        *reinterpret_cast<uint4*>(reinterpret_cast<char*>(&dp[n * P]) + c * 16) = srcp[n * 16 + c];
    }
    __syncthreads();

    // ---- mainloop: 8 k-steps of 16, 3-term bf16 split product ----
    wmma::fragment<wmma::accumulator, 16, 16, 16, float> acc[2][NC];
#pragma unroll
    for (int i = 0; i < 2; ++i)
#pragma unroll
        for (int j = 0; j < NC; ++j) wmma::fill_fragment(acc[i][j], 0.0f);

#pragma unroll
    for (int ks = 0; ks < 8; ++ks) {
        const int k = ks * 16;
        wmma::fragment<wmma::matrix_a, 16, 16, 16, __nv_bfloat16, wmma::row_major> ah[2], al[2];
        wmma::fragment<wmma::matrix_b, 16, 16, 16, __nv_bfloat16, wmma::col_major> bh[NC], bl[NC];
#pragma unroll
        for (int i = 0; i < 2; ++i) {
            int m = wr * 32 + i * 16;
            wmma::load_matrix_sync(ah[i], &Ahi[m * P + k], P);
            wmma::load_matrix_sync(al[i], &Alo[m * P + k], P);
        }
#pragma unroll
        for (int j = 0; j < NC; ++j) {
            int n = wc * (BN / 4) + j * 16;
            wmma::load_matrix_sync(bh[j], &Whi[n * P + k], P);
            wmma::load_matrix_sync(bl[j], &Wlo[n * P + k], P);
        }
#pragma unroll
        for (int i = 0; i < 2; ++i)
#pragma unroll
            for (int j = 0; j < NC; ++j) {
                wmma::mma_sync(acc[i][j], ah[i], bh[j], acc[i][j]);
                wmma::mma_sync(acc[i][j], ah[i], bl[j], acc[i][j]);
                wmma::mma_sync(acc[i][j], al[i], bh[j], acc[i][j]);
            }
    }

    // ---- epilogue: frags -> smem f32 -> (bias) -> gmem float4 ----
    __syncthreads();   // done reading A/W smem
#pragma unroll
    for (int i = 0; i < 2; ++i)
#pragma unroll
        for (int j = 0; j < NC; ++j) {
            int m = wr * 32 + i * 16;
            int n = wc * (BN / 4) + j * 16;
            wmma::store_matrix_sync(&Cs[m * CP + n], acc[i][j], CP, wmma::mem_row_major);
        }
    __syncthreads();

#pragma unroll
    for (int i = 0; i < BN / 16; ++i) {
        int idx = tid + i * 512;          // 128 * BN/4 float4s
        int r   = idx / (BN / 4);
        int c   = (idx % (BN / 4)) * 4;
        int gm  = m0 + r;
        if (gm >= M) continue;
        float4 o = *reinterpret_cast<const float4*>(&Cs[r * CP + c]);
        if (BIAS) {
            o.x += bias[c + 0]; o.y += bias[c + 1];
            o.z += bias[c + 2]; o.w += bias[c + 3];
        }
        *reinterpret_cast<float4*>(C + (size_t)gm * BN + c) = o;
    }
}

// ---------------- graph kernels ----------------
__global__ void zero_k(float4* __restrict__ p, int n4) {
    int i = blockIdx.x * blockDim.x + threadIdx.x;
    if (i < n4) p[i] = make_float4(0.f, 0.f, 0.f, 0.f);
}

__global__ void deg_k(const int* __restrict__ dst) {
    int e = blockIdx.x * blockDim.x + threadIdx.x;
    if (e < NE) atomicAdd(&g_deg[dst[e]], 1.0f);
}

__global__ void inv_k() {
    int i = blockIdx.x * blockDim.x + threadIdx.x;
    if (i < NN) g_deg[i] = 1.0f / fmaxf(g_deg[i], 1.0f);
}

__device__ __forceinline__ void red4(float* p, float4 v) {
    asm volatile("red.global.add.v4.f32 [%0], {%1, %2, %3, %4};"
                 :: "l"(p), "f"(v.x), "f"(v.y), "f"(v.z), "f"(v.w) : "memory");
}

// out[dst[e]] += p[src[e]] * invdeg[dst[e]]   (out pre-initialized with self term + bias)
template<int DW>
__global__ void scatter_k(const float* __restrict__ p, const int* __restrict__ src,
                          const int* __restrict__ dst, float* __restrict__ out) {
    const int PV = DW / 4;
    int t = blockIdx.x * blockDim.x + threadIdx.x;
    int e = t / PV;
    if (e >= NE) return;
    int c = (t % PV) * 4;
    int sn = src[e];
    int dn = dst[e];
    float inv = g_deg[dn];
    float4 v = *reinterpret_cast<const float4*>(p + (size_t)sn * DW + c);
    v.x *= inv; v.y *= inv; v.z *= inv; v.w *= inv;
    red4(out + (size_t)dn * DW + c, v);
}

// ---------------- launch ----------------
extern "C" void kernel_launch(void* const* d_in, const int* in_sizes, int n_in,
                              void* d_out, int out_size) {
    const float* x        = (const float*)d_in[0];
    const int*   src      = (const int*)  d_in[1];
    const int*   dst      = (const int*)  d_in[2];
    const float* w_self0  = (const float*)d_in[3];
    const float* b_self0  = (const float*)d_in[4];
    const float* w_neigh0 = (const float*)d_in[5];
    const float* fc_w     = (const float*)d_in[6];
    const float* fc_b     = (const float*)d_in[7];
    const float* fc2_w    = (const float*)d_in[8];
    const float* fc2_b    = (const float*)d_in[9];
    const float* w_self1  = (const float*)d_in[10];
    const float* b_self1  = (const float*)d_in[11];
    const float* w_neigh1 = (const float*)d_in[12];
    const float* w_self2  = (const float*)d_in[13];
    const float* b_self2  = (const float*)d_in[14];
    const float* w_neigh2 = (const float*)d_in[15];
    float* out = (float*)d_out;

    float *p_a, *p_b, *p_p, *p_deg;
    __nv_bfloat16* p_wb;
    cudaGetSymbolAddress((void**)&p_a,   g_a);
    cudaGetSymbolAddress((void**)&p_b,   g_b);
    cudaGetSymbolAddress((void**)&p_p,   g_p);
    cudaGetSymbolAddress((void**)&p_deg, g_deg);
    cudaGetSymbolAddress((void**)&p_wb,  g_wb);

    const __nv_bfloat16 *s0h = p_wb,          *s0l = p_wb + 16384;
    const __nv_bfloat16 *n0h = p_wb + 32768,  *n0l = p_wb + 49152;
    const __nv_bfloat16 *fch = p_wb + 65536,  *fcl = p_wb + 81920;
    const __nv_bfloat16 *f2h = p_wb + 98304,  *f2l = p_wb + 114688;
    const __nv_bfloat16 *s1h = p_wb + 131072, *s1l = p_wb + 147456;
    const __nv_bfloat16 *n1h = p_wb + 163840, *n1l = p_wb + 180224;
    const __nv_bfloat16 *s2h = p_wb + 196608, *s2l = p_wb + 204800;
    const __nv_bfloat16 *n2h = p_wb + 212992, *n2l = p_wb + 221184;

    const int s128 = (2 * 128 * 136 + 2 * 128 * 136) * 2;   // 139264
    const int s64  = (2 * 128 * 136 + 2 * 64  * 136) * 2;   // 104448
    cudaFuncSetAttribute(mm_k<128, false, true >, cudaFuncAttributeMaxDynamicSharedMemorySize, s128);
    cudaFuncSetAttribute(mm_k<128, false, false>, cudaFuncAttributeMaxDynamicSharedMemorySize, s128);
    cudaFuncSetAttribute(mm_k<128, true,  true >, cudaFuncAttributeMaxDynamicSharedMemorySize, s128);
    cudaFuncSetAttribute(mm_k<128, true,  false>, cudaFuncAttributeMaxDynamicSharedMemorySize, s128);
    cudaFuncSetAttribute(mm_k<64,  true,  true >, cudaFuncAttributeMaxDynamicSharedMemorySize, s64);
    cudaFuncSetAttribute(mm_k<64,  true,  false>, cudaFuncAttributeMaxDynamicSharedMemorySize, s64);

    const int GB = (NN + 127) / 128;   // 782
    const int T  = 256;

    // ---- prep: degrees -> inverse, weight preconversion ----
    zero_k<<<(NN / 4 + T - 1) / T, T>>>((float4*)p_deg, NN / 4);
    deg_k<<<(NE + T - 1) / T, T>>>(dst);
    inv_k<<<(NN + T - 1) / T, T>>>();
    WSrc ws; ws.s[0] = w_self0; ws.s[1] = w_neigh0; ws.s[2] = fc_w; ws.s[3] = fc2_w;
             ws.s[4] = w_self1; ws.s[5] = w_neigh1; ws.s[6] = w_self2; ws.s[7] = w_neigh2;
    wconv_k<<<(114688 + T - 1) / T, T>>>(ws);

    // ---- layer 0: NGNN SAGEConv (relu fused into consumers' A-load) ----
    mm_k<128, false, true ><<<GB, 512, s128>>>(x, s0h, s0l, b_self0, p_a, NN);
    mm_k<128, false, false><<<GB, 512, s128>>>(x, n0h, n0l, nullptr, p_p, NN);
    scatter_k<128><<<(NE * 32 + T - 1) / T, T>>>(p_p, src, dst, p_a);      // p_a = conv0 (pre-relu)
    mm_k<128, true, true><<<GB, 512, s128>>>(p_a, fch, fcl, fc_b,  p_b, NN);
    mm_k<128, true, true><<<GB, 512, s128>>>(p_b, f2h, f2l, fc2_b, p_a, NN);

    // ---- layer 1: SAGEConv ----
    mm_k<128, true, true ><<<GB, 512, s128>>>(p_a, s1h, s1l, b_self1, p_b, NN);
    mm_k<128, true, false><<<GB, 512, s128>>>(p_a, n1h, n1l, nullptr, p_p, NN);
    scatter_k<128><<<(NE * 32 + T - 1) / T, T>>>(p_p, src, dst, p_b);      // p_b = conv1 (pre-relu)

    // ---- layer 2 (output, width 64) ----
    mm_k<64, true, true ><<<GB, 512, s64>>>(p_b, s2h, s2l, b_self2, out, NN);
    mm_k<64, true, false><<<GB, 512, s64>>>(p_b, n2h, n2l, nullptr, p_p, NN);
    scatter_k<64><<<(NE * 16 + T - 1) / T, T>>>(p_p, src, dst, out);
}

// round 6
// speedup vs baseline: 1.2996x; 1.0690x over previous
#include <cuda_runtime.h>
#include <cuda_bf16.h>
#include <mma.h>
#include <cstdint>

using namespace nvcuda;

#define NN 100000
#define NE 600000

// ---------------- scratch (device globals; no allocation allowed) ----------------
__device__ float g_a  [(size_t)NN * 128];
__device__ float g_b  [(size_t)NN * 128];
__device__ float g_p  [(size_t)NN * 128];
__device__ float g_deg[NN];
__device__ __nv_bfloat16 g_wb[229376];   // 7 logical weight blocks (layer2 pair packed), transposed, hi+lo

// split fp32 -> (hi bf16, lo bf16)
__device__ __forceinline__ void split2(float a, float b, uint32_t& hi, uint32_t& lo) {
    __nv_bfloat16 ha = __float2bfloat16(a), hb = __float2bfloat16(b);
    float ra = a - __bfloat162float(ha), rb = b - __bfloat162float(hb);
    __nv_bfloat16 la = __float2bfloat16(ra), lb = __float2bfloat16(rb);
    hi = ((uint32_t)__bfloat16_as_ushort(hb) << 16) | (uint32_t)__bfloat16_as_ushort(ha);
    lo = ((uint32_t)__bfloat16_as_ushort(lb) << 16) | (uint32_t)__bfloat16_as_ushort(la);
}

// ---------------- weight conversion: W[k][n] f32 -> transposed bf16 hi/lo [n*128+k] ----
// blocks: self0@0 neigh0@32768 fc@65536 fc2@98304 self1@131072 neigh1@163840
//         layer2 combined @196608 (hi 128x128: self2 cols 0-63, neigh2 cols 64-127; lo @+16384)
struct WSrc { const float* s[8]; };

__global__ void wconv_k(WSrc ws) {
    int idx = blockIdx.x * blockDim.x + threadIdx.x;
    if (idx >= 114688) return;
    int m, r, ncols;
    if (idx < 98304) { m = idx >> 14; r = idx & 16383; ncols = 128; }
    else             { m = 6 + ((idx - 98304) >> 13); r = (idx - 98304) & 8191; ncols = 64; }
    int k = r / ncols, n = r % ncols;
    float v = ws.s[m][r];
    __nv_bfloat16 h = __float2bfloat16(v);
    __nv_bfloat16 l = __float2bfloat16(v - __bfloat162float(h));
    int base, nc;
    if (m < 6)      { const int offs[6] = {0, 32768, 65536, 98304, 131072, 163840};
                      base = offs[m]; nc = n; }
    else if (m == 6){ base = 196608; nc = n; }       // self2 -> cols 0..63
    else            { base = 196608; nc = 64 + n; }  // neigh2 -> cols 64..127
    int half = (m < 6) ? 16384 : 16384;
    g_wb[base + nc * 128 + k]        = h;
    g_wb[base + half + nc * 128 + k] = l;
}

// ---------------- WMMA bf16 GEMM: 64-row tile x 128 cols, 256 thr, 2 CTAs/SM ----
// C = [relu-in](A)[M,128] @ W[128,128] ; cols < SPL -> C1 (+bias1), cols >= SPL -> C2.
// 3-term bf16 split (hi*hi + hi*lo + lo*hi), fp32 accumulate.
template<int SPL, bool RIN, bool B1>
__global__ __launch_bounds__(256, 2)
void mm_k(const float* __restrict__ A,
          const __nv_bfloat16* __restrict__ whi, const __nv_bfloat16* __restrict__ wlo,
          const float* __restrict__ bias1, float* __restrict__ C1, float* __restrict__ C2, int M)
{
    extern __shared__ char dsm[];
    constexpr int P   = 136;                 // bf16 pitch
    constexpr int ASZ = 64 * P * 2;          // 17408 B per A half
    constexpr int CP  = 132;                 // f32 epilogue pitch

    __nv_bfloat16* Ahi = reinterpret_cast<__nv_bfloat16*>(dsm);
    __nv_bfloat16* Alo = reinterpret_cast<__nv_bfloat16*>(dsm + ASZ);
    __nv_bfloat16* Whi = reinterpret_cast<__nv_bfloat16*>(dsm + 2 * ASZ);
    __nv_bfloat16* Wlo = reinterpret_cast<__nv_bfloat16*>(dsm + 2 * ASZ + 128 * P * 2);
    float*         Cs  = reinterpret_cast<float*>(dsm);

    const int tid = threadIdx.x;
    const int wid = tid >> 5;
    const int wr  = wid & 1;                 // row group: rows wr*32
    const int wc  = wid >> 1;                // col group: cols wc*32
    const int m0  = blockIdx.x * 64;

    // ---- A tile: f32 coalesced float4, optional relu, hi/lo split ----
#pragma unroll
    for (int i = 0; i < 8; ++i) {
        int idx = tid + i * 256;             // 2048 float4s
        int m   = idx >> 5;
        int k0  = (idx & 31) * 4;
        float4 v = make_float4(0.f, 0.f, 0.f, 0.f);
        int gm = m0 + m;
        if (gm < M) v = *reinterpret_cast<const float4*>(A + (size_t)gm * 128 + k0);
        if (RIN) { v.x = fmaxf(v.x, 0.f); v.y = fmaxf(v.y, 0.f); v.z = fmaxf(v.z, 0.f); v.w = fmaxf(v.w, 0.f); }
        uint32_t h0, l0, h1, l1;
        split2(v.x, v.y, h0, l0);
        split2(v.z, v.w, h1, l1);
        *reinterpret_cast<uint2*>(&Ahi[m * P + k0]) = make_uint2(h0, h1);
        *reinterpret_cast<uint2*>(&Alo[m * P + k0]) = make_uint2(l0, l1);
    }

    // ---- W tile: preconverted bf16, uint4 copy with repitch (128 -> P) ----
#pragma unroll
    for (int i = 0; i < 16; ++i) {           // 2 * 2048 uint4 / 256 thr
        int idx  = tid + i * 256;
        int half = idx >> 11;
        int r    = idx & 2047;
        int n    = r >> 4;
        int c    = r & 15;
        const uint4* srcp = reinterpret_cast<const uint4*>(half ? wlo : whi);
        __nv_bfloat16* dp = half ? Wlo : Whi;
        *reinterpret_cast<uint4*>(reinterpret_cast<char*>(&dp[n * P]) + c * 16) = srcp[n * 16 + c];
    }
    __syncthreads();

    // ---- mainloop: 8 k-steps, 3-term split product, warp tile 32x32 ----
    wmma::fragment<wmma::accumulator, 16, 16, 16, float> acc[2][2];
#pragma unroll
    for (int i = 0; i < 2; ++i)
#pragma unroll
        for (int j = 0; j < 2; ++j) wmma::fill_fragment(acc[i][j], 0.0f);

#pragma unroll
    for (int ks = 0; ks < 8; ++ks) {
        const int k = ks * 16;
        wmma::fragment<wmma::matrix_a, 16, 16, 16, __nv_bfloat16, wmma::row_major> ah[2], al[2];
        wmma::fragment<wmma::matrix_b, 16, 16, 16, __nv_bfloat16, wmma::col_major> bh[2], bl[2];
#pragma unroll
        for (int i = 0; i < 2; ++i) {
            int m = wr * 32 + i * 16;
            wmma::load_matrix_sync(ah[i], &Ahi[m * P + k], P);
            wmma::load_matrix_sync(al[i], &Alo[m * P + k], P);
        }
#pragma unroll
        for (int j = 0; j < 2; ++j) {
            int n = wc * 32 + j * 16;
            wmma::load_matrix_sync(bh[j], &Whi[n * P + k], P);
            wmma::load_matrix_sync(bl[j], &Wlo[n * P + k], P);
        }
#pragma unroll
        for (int i = 0; i < 2; ++i)
#pragma unroll
            for (int j = 0; j < 2; ++j) {
                wmma::mma_sync(acc[i][j], ah[i], bh[j], acc[i][j]);
                wmma::mma_sync(acc[i][j], ah[i], bl[j], acc[i][j]);
                wmma::mma_sync(acc[i][j], al[i], bh[j], acc[i][j]);
            }
    }

    // ---- epilogue: frags -> smem f32 -> bias/route -> gmem float4 ----
    __syncthreads();
#pragma unroll
    for (int i = 0; i < 2; ++i)
#pragma unroll
        for (int j = 0; j < 2; ++j)
            wmma::store_matrix_sync(&Cs[(wr * 32 + i * 16) * CP + wc * 32 + j * 16], acc[i][j], CP, wmma::mem_row_major);
    __syncthreads();

#pragma unroll
    for (int i = 0; i < 8; ++i) {
        int idx = tid + i * 256;             // 64 rows x 32 f4
        int r   = idx >> 5;
        int c   = (idx & 31) * 4;
        int gm  = m0 + r;
        if (gm >= M) continue;
        float4 o = *reinterpret_cast<const float4*>(&Cs[r * CP + c]);
        if (SPL == 128 || c < SPL) {
            if (B1) {
                o.x += bias1[c + 0]; o.y += bias1[c + 1];
                o.z += bias1[c + 2]; o.w += bias1[c + 3];
            }
            *reinterpret_cast<float4*>(C1 + (size_t)gm * SPL + c) = o;
        } else {
            *reinterpret_cast<float4*>(C2 + (size_t)gm * (128 - SPL) + (c - SPL)) = o;
        }
    }
}

// ---------------- graph kernels ----------------
__global__ void zero_k(float4* __restrict__ p, int n4) {
    int i = blockIdx.x * blockDim.x + threadIdx.x;
    if (i < n4) p[i] = make_float4(0.f, 0.f, 0.f, 0.f);
}

__global__ void deg_k(const int* __restrict__ dst) {
    int e = blockIdx.x * blockDim.x + threadIdx.x;
    if (e < NE) atomicAdd(&g_deg[dst[e]], 1.0f);
}

__global__ void inv_k() {
    int i = blockIdx.x * blockDim.x + threadIdx.x;
    if (i < NN) g_deg[i] = 1.0f / fmaxf(g_deg[i], 1.0f);
}

__device__ __forceinline__ void red4(float* p, float4 v) {
    asm volatile("red.global.add.v4.f32 [%0], {%1, %2, %3, %4};"
                 :: "l"(p), "f"(v.x), "f"(v.y), "f"(v.z), "f"(v.w) : "memory");
}

// out[dst[e]] += p[src[e]] * invdeg[dst[e]]   (out pre-initialized with self term + bias)
template<int DW>
__global__ void scatter_k(const float* __restrict__ p, const int* __restrict__ src,
                          const int* __restrict__ dst, float* __restrict__ out) {
    const int PV = DW / 4;
    int t = blockIdx.x * blockDim.x + threadIdx.x;
    int e = t / PV;
    if (e >= NE) return;
    int c = (t % PV) * 4;
    int sn = src[e];
    int dn = dst[e];
    float inv = g_deg[dn];
    float4 v = *reinterpret_cast<const float4*>(p + (size_t)sn * DW + c);
    v.x *= inv; v.y *= inv; v.z *= inv; v.w *= inv;
    red4(out + (size_t)dn * DW + c, v);
}

// ---------------- launch ----------------
extern "C" void kernel_launch(void* const* d_in, const int* in_sizes, int n_in,
                              void* d_out, int out_size) {
    const float* x        = (const float*)d_in[0];
    const int*   src      = (const int*)  d_in[1];
    const int*   dst      = (const int*)  d_in[2];
    const float* w_self0  = (const float*)d_in[3];
    const float* b_self0  = (const float*)d_in[4];
    const float* w_neigh0 = (const float*)d_in[5];
    const float* fc_w     = (const float*)d_in[6];
    const float* fc_b     = (const float*)d_in[7];
    const float* fc2_w    = (const float*)d_in[8];
    const float* fc2_b    = (const float*)d_in[9];
    const float* w_self1  = (const float*)d_in[10];
    const float* b_self1  = (const float*)d_in[11];
    const float* w_neigh1 = (const float*)d_in[12];
    const float* w_self2  = (const float*)d_in[13];
    const float* b_self2  = (const float*)d_in[14];
    const float* w_neigh2 = (const float*)d_in[15];
    float* out = (float*)d_out;

    float *p_a, *p_b, *p_p, *p_deg;
    __nv_bfloat16* p_wb;
    cudaGetSymbolAddress((void**)&p_a,   g_a);
    cudaGetSymbolAddress((void**)&p_b,   g_b);
    cudaGetSymbolAddress((void**)&p_p,   g_p);
    cudaGetSymbolAddress((void**)&p_deg, g_deg);
    cudaGetSymbolAddress((void**)&p_wb,  g_wb);

    const __nv_bfloat16 *s0h = p_wb,          *s0l = p_wb + 16384;
    const __nv_bfloat16 *n0h = p_wb + 32768,  *n0l = p_wb + 49152;
    const __nv_bfloat16 *fch = p_wb + 65536,  *fcl = p_wb + 81920;
    const __nv_bfloat16 *f2h = p_wb + 98304,  *f2l = p_wb + 114688;
    const __nv_bfloat16 *s1h = p_wb + 131072, *s1l = p_wb + 147456;
    const __nv_bfloat16 *n1h = p_wb + 163840, *n1l = p_wb + 180224;
    const __nv_bfloat16 *l2h = p_wb + 196608, *l2l = p_wb + 212992;

    const int smem = (2 * 64 * 136 + 2 * 128 * 136) * 2;   // 104448
    cudaFuncSetAttribute(mm_k<128, false, true >, cudaFuncAttributeMaxDynamicSharedMemorySize, smem);
    cudaFuncSetAttribute(mm_k<128, false, false>, cudaFuncAttributeMaxDynamicSharedMemorySize, smem);
    cudaFuncSetAttribute(mm_k<128, true,  true >, cudaFuncAttributeMaxDynamicSharedMemorySize, smem);
    cudaFuncSetAttribute(mm_k<128, true,  false>, cudaFuncAttributeMaxDynamicSharedMemorySize, smem);
    cudaFuncSetAttribute(mm_k<64,  true,  true >, cudaFuncAttributeMaxDynamicSharedMemorySize, smem);

    const int GB = (NN + 63) / 64;   // 1563
    const int T  = 256;

    // ---- prep: degrees -> inverse, weight preconversion ----
    zero_k<<<(NN / 4 + T - 1) / T, T>>>((float4*)p_deg, NN / 4);
    deg_k<<<(NE + T - 1) / T, T>>>(dst);
    inv_k<<<(NN + T - 1) / T, T>>>();
    WSrc ws; ws.s[0] = w_self0; ws.s[1] = w_neigh0; ws.s[2] = fc_w; ws.s[3] = fc2_w;
             ws.s[4] = w_self1; ws.s[5] = w_neigh1; ws.s[6] = w_self2; ws.s[7] = w_neigh2;
    wconv_k<<<(114688 + T - 1) / T, T>>>(ws);

    // ---- layer 0: NGNN SAGEConv (relu fused into consumers' A-load) ----
    mm_k<128, false, true ><<<GB, T, smem>>>(x, s0h, s0l, b_self0, p_a, nullptr, NN);
    mm_k<128, false, false><<<GB, T, smem>>>(x, n0h, n0l, nullptr, p_p, nullptr, NN);
    scatter_k<128><<<(NE * 32 + T - 1) / T, T>>>(p_p, src, dst, p_a);      // p_a = conv0 (pre-relu)
    mm_k<128, true, true><<<GB, T, smem>>>(p_a, fch, fcl, fc_b,  p_b, nullptr, NN);
    mm_k<128, true, true><<<GB, T, smem>>>(p_b, f2h, f2l, fc2_b, p_a, nullptr, NN);

    // ---- layer 1: SAGEConv ----
    mm_k<128, true, true ><<<GB, T, smem>>>(p_a, s1h, s1l, b_self1, p_b, nullptr, NN);
    mm_k<128, true, false><<<GB, T, smem>>>(p_a, n1h, n1l, nullptr, p_p, nullptr, NN);
    scatter_k<128><<<(NE * 32 + T - 1) / T, T>>>(p_p, src, dst, p_b);      // p_b = conv1 (pre-relu)

    // ---- layer 2 (output): one pass, cols 0-63 -> out (+bias), 64-127 -> p_p ----
    mm_k<64, true, true><<<GB, T, smem>>>(p_b, l2h, l2l, b_self2, out, p_p, NN);
    scatter_k<64><<<(NE * 16 + T - 1) / T, T>>>(p_p, src, dst, out);
}

// round 7
// speedup vs baseline: 1.3879x; 1.0679x over previous
#include <cuda_runtime.h>
#include <cuda_bf16.h>
#include <mma.h>
#include <cstdint>

using namespace nvcuda;

#define NN 100000
#define NE 600000

// ---------------- scratch (device globals; no allocation allowed) ----------------
__device__ float g_a  [(size_t)NN * 128];
__device__ float g_b  [(size_t)NN * 128];
__device__ float g_p  [(size_t)NN * 128];
__device__ float g_deg[NN];
__device__ __nv_bfloat16 g_wb[229376];   // 7 weight blocks (layer2 pair packed to 128 cols), transposed, hi+lo

// smem layout (bytes): Ahi@0, Alo@17408, Whi@34816, Wlo@69632  -> total 104448
// f32 staging (64 x 132) overlays the W region (33792 B <= 69632 OK)
#define PP    136
#define ASZ   17408
#define WOFF  34816
#define SMEMB 104448
#define CP    132

// split fp32 -> (hi bf16, lo bf16) packed pairs
__device__ __forceinline__ void split2(float a, float b, uint32_t& hi, uint32_t& lo) {
    __nv_bfloat16 ha = __float2bfloat16(a), hb = __float2bfloat16(b);
    float ra = a - __bfloat162float(ha), rb = b - __bfloat162float(hb);
    __nv_bfloat16 la = __float2bfloat16(ra), lb = __float2bfloat16(rb);
    hi = ((uint32_t)__bfloat16_as_ushort(hb) << 16) | (uint32_t)__bfloat16_as_ushort(ha);
    lo = ((uint32_t)__bfloat16_as_ushort(lb) << 16) | (uint32_t)__bfloat16_as_ushort(la);
}

// ---------------- weight conversion: W[k][n] f32 -> transposed bf16 hi/lo [n*128+k] ----
struct WSrc { const float* s[8]; };

__global__ void wconv_k(WSrc ws) {
    int idx = blockIdx.x * blockDim.x + threadIdx.x;
    if (idx >= 114688) return;
    int m, r, ncols;
    if (idx < 98304) { m = idx >> 14; r = idx & 16383; ncols = 128; }
    else             { m = 6 + ((idx - 98304) >> 13); r = (idx - 98304) & 8191; ncols = 64; }
    int k = r / ncols, n = r % ncols;
    float v = ws.s[m][r];
    __nv_bfloat16 h = __float2bfloat16(v);
    __nv_bfloat16 l = __float2bfloat16(v - __bfloat162float(h));
    int base, nc;
    if (m < 6)      { const int offs[6] = {0, 32768, 65536, 98304, 131072, 163840};
                      base = offs[m]; nc = n; }
    else if (m == 6){ base = 196608; nc = n; }       // self2 -> cols 0..63
    else            { base = 196608; nc = 64 + n; }  // neigh2 -> cols 64..127
    g_wb[base + nc * 128 + k]         = h;
    g_wb[base + 16384 + nc * 128 + k] = l;
}

// ================= device building blocks (64-row tile, 256 threads, 8 warps) =================

// A tile from global f32 (optional relu), split -> Ahi/Alo smem
template<bool RELU>
__device__ __forceinline__ void loadA(char* dsm, const float* __restrict__ A, int m0, int M, int tid) {
    __nv_bfloat16* Ahi = reinterpret_cast<__nv_bfloat16*>(dsm);
    __nv_bfloat16* Alo = reinterpret_cast<__nv_bfloat16*>(dsm + ASZ);
#pragma unroll
    for (int i = 0; i < 8; ++i) {
        int idx = tid + i * 256;
        int m   = idx >> 5;
        int k0  = (idx & 31) * 4;
        float4 v = make_float4(0.f, 0.f, 0.f, 0.f);
        int gm = m0 + m;
        if (gm < M) v = *reinterpret_cast<const float4*>(A + (size_t)gm * 128 + k0);
        if (RELU) { v.x = fmaxf(v.x, 0.f); v.y = fmaxf(v.y, 0.f); v.z = fmaxf(v.z, 0.f); v.w = fmaxf(v.w, 0.f); }
        uint32_t h0, l0, h1, l1;
        split2(v.x, v.y, h0, l0);
        split2(v.z, v.w, h1, l1);
        *reinterpret_cast<uint2*>(&Ahi[m * PP + k0]) = make_uint2(h0, h1);
        *reinterpret_cast<uint2*>(&Alo[m * PP + k0]) = make_uint2(l0, l1);
    }
}

// W tile (preconverted bf16 hi/lo, 128 cols) -> Whi/Wlo smem, uint4 repitch copy
__device__ __forceinline__ void loadW(char* dsm, const __nv_bfloat16* __restrict__ whi,
                                      const __nv_bfloat16* __restrict__ wlo, int tid) {
    __nv_bfloat16* Whi = reinterpret_cast<__nv_bfloat16*>(dsm + WOFF);
    __nv_bfloat16* Wlo = reinterpret_cast<__nv_bfloat16*>(dsm + WOFF + ASZ * 2);
#pragma unroll
    for (int i = 0; i < 16; ++i) {
        int idx  = tid + i * 256;         // 2 * 2048 uint4
        int half = idx >> 11;
        int r    = idx & 2047;
        int n    = r >> 4;
        int c    = r & 15;
        const uint4* srcp = reinterpret_cast<const uint4*>(half ? wlo : whi);
        __nv_bfloat16* dp = half ? Wlo : Whi;
        *reinterpret_cast<uint4*>(reinterpret_cast<char*>(&dp[n * PP]) + c * 16) = srcp[n * 16 + c];
    }
}

typedef wmma::fragment<wmma::accumulator, 16, 16, 16, float> AccF;

// mainloop: 64x128 = A(64x128) @ W(128x128), warp tile 32x32 (wr=wid&1, wc=wid>>1)
__device__ __forceinline__ void mmaStage(char* dsm, AccF acc[2][2], int wr, int wc) {
    __nv_bfloat16* Ahi = reinterpret_cast<__nv_bfloat16*>(dsm);
    __nv_bfloat16* Alo = reinterpret_cast<__nv_bfloat16*>(dsm + ASZ);
    __nv_bfloat16* Whi = reinterpret_cast<__nv_bfloat16*>(dsm + WOFF);
    __nv_bfloat16* Wlo = reinterpret_cast<__nv_bfloat16*>(dsm + WOFF + ASZ * 2);
#pragma unroll
    for (int i = 0; i < 2; ++i)
#pragma unroll
        for (int j = 0; j < 2; ++j) wmma::fill_fragment(acc[i][j], 0.0f);
#pragma unroll
    for (int ks = 0; ks < 8; ++ks) {
        const int k = ks * 16;
        wmma::fragment<wmma::matrix_a, 16, 16, 16, __nv_bfloat16, wmma::row_major> ah[2], al[2];
        wmma::fragment<wmma::matrix_b, 16, 16, 16, __nv_bfloat16, wmma::col_major> bh[2], bl[2];
#pragma unroll
        for (int i = 0; i < 2; ++i) {
            int m = wr * 32 + i * 16;
            wmma::load_matrix_sync(ah[i], &Ahi[m * PP + k], PP);
            wmma::load_matrix_sync(al[i], &Alo[m * PP + k], PP);
        }
#pragma unroll
        for (int j = 0; j < 2; ++j) {
            int n = wc * 32 + j * 16;
            wmma::load_matrix_sync(bh[j], &Whi[n * PP + k], PP);
            wmma::load_matrix_sync(bl[j], &Wlo[n * PP + k], PP);
        }
#pragma unroll
        for (int i = 0; i < 2; ++i)
#pragma unroll
            for (int j = 0; j < 2; ++j) {
                wmma::mma_sync(acc[i][j], ah[i], bh[j], acc[i][j]);
                wmma::mma_sync(acc[i][j], ah[i], bl[j], acc[i][j]);
                wmma::mma_sync(acc[i][j], al[i], bh[j], acc[i][j]);
            }
    }
}

// accs -> f32 staging (overlays W region). Caller syncs before (W reads done) and after.
__device__ __forceinline__ void accToStaging(char* dsm, AccF acc[2][2], int wr, int wc) {
    float* Cs = reinterpret_cast<float*>(dsm + WOFF);
#pragma unroll
    for (int i = 0; i < 2; ++i)
#pragma unroll
        for (int j = 0; j < 2; ++j)
            wmma::store_matrix_sync(&Cs[(wr * 32 + i * 16) * CP + wc * 32 + j * 16], acc[i][j], CP, wmma::mem_row_major);
}

// staging -> (+bias, relu) -> split -> Ahi/Alo (next stage's A)
__device__ __forceinline__ void stagingToA(char* dsm, const float* __restrict__ bias, int tid) {
    const float* Cs = reinterpret_cast<const float*>(dsm + WOFF);
    __nv_bfloat16* Ahi = reinterpret_cast<__nv_bfloat16*>(dsm);
    __nv_bfloat16* Alo = reinterpret_cast<__nv_bfloat16*>(dsm + ASZ);
#pragma unroll
    for (int i = 0; i < 8; ++i) {
        int idx = tid + i * 256;
        int m   = idx >> 5;
        int c   = (idx & 31) * 4;
        float4 v = *reinterpret_cast<const float4*>(&Cs[m * CP + c]);
        v.x = fmaxf(v.x + bias[c + 0], 0.f);
        v.y = fmaxf(v.y + bias[c + 1], 0.f);
        v.z = fmaxf(v.z + bias[c + 2], 0.f);
        v.w = fmaxf(v.w + bias[c + 3], 0.f);
        uint32_t h0, l0, h1, l1;
        split2(v.x, v.y, h0, l0);
        split2(v.z, v.w, h1, l1);
        *reinterpret_cast<uint2*>(&Ahi[m * PP + c]) = make_uint2(h0, h1);
        *reinterpret_cast<uint2*>(&Alo[m * PP + c]) = make_uint2(l0, l1);
    }
}

// staging -> global (optional bias), full 128 cols
template<bool BIAS>
__device__ __forceinline__ void stagingToGlobal(char* dsm, const float* __restrict__ bias,
                                                float* __restrict__ C, int m0, int M, int tid) {
    const float* Cs = reinterpret_cast<const float*>(dsm + WOFF);
#pragma unroll
    for (int i = 0; i < 8; ++i) {
        int idx = tid + i * 256;
        int m   = idx >> 5;
        int c   = (idx & 31) * 4;
        int gm  = m0 + m;
        if (gm >= M) continue;
        float4 o = *reinterpret_cast<const float4*>(&Cs[m * CP + c]);
        if (BIAS) { o.x += bias[c]; o.y += bias[c + 1]; o.z += bias[c + 2]; o.w += bias[c + 3]; }
        *reinterpret_cast<float4*>(C + (size_t)gm * 128 + c) = o;
    }
}

// ================= fused kernels =================

// K1: x -> self0 (+b) -> p_a ; neigh0 -> p_p
__global__ __launch_bounds__(256, 2)
void k1_k(const float* __restrict__ x,
          const __nv_bfloat16* __restrict__ s0h, const __nv_bfloat16* __restrict__ s0l,
          const __nv_bfloat16* __restrict__ n0h, const __nv_bfloat16* __restrict__ n0l,
          const float* __restrict__ b0, float* __restrict__ Ca, float* __restrict__ Cp, int M)
{
    extern __shared__ char dsm[];
    const int tid = threadIdx.x, wid = tid >> 5, wr = wid & 1, wc = wid >> 1;
    const int m0 = blockIdx.x * 64;
    AccF acc[2][2];

    loadA<false>(dsm, x, m0, M, tid);
    loadW(dsm, s0h, s0l, tid);
    __syncthreads();
    mmaStage(dsm, acc, wr, wc);
    __syncthreads();
    accToStaging(dsm, acc, wr, wc);
    __syncthreads();
    stagingToGlobal<true>(dsm, b0, Ca, m0, M, tid);
    __syncthreads();
    loadW(dsm, n0h, n0l, tid);
    __syncthreads();
    mmaStage(dsm, acc, wr, wc);
    __syncthreads();
    accToStaging(dsm, acc, wr, wc);
    __syncthreads();
    stagingToGlobal<false>(dsm, nullptr, Cp, m0, M, tid);
}

// K2: relu(conv0) -> fc(+b,relu) -> fc2(+b,relu) -> { self1(+b)->p_b ; neigh1->p_p }
__global__ __launch_bounds__(256, 2)
void k2_k(const float* __restrict__ Ain,
          const __nv_bfloat16* __restrict__ fch, const __nv_bfloat16* __restrict__ fcl, const float* __restrict__ fcb,
          const __nv_bfloat16* __restrict__ f2h, const __nv_bfloat16* __restrict__ f2l, const float* __restrict__ f2b,
          const __nv_bfloat16* __restrict__ s1h, const __nv_bfloat16* __restrict__ s1l, const float* __restrict__ b1,
          const __nv_bfloat16* __restrict__ n1h, const __nv_bfloat16* __restrict__ n1l,
          float* __restrict__ Cb, float* __restrict__ Cp, int M)
{
    extern __shared__ char dsm[];
    const int tid = threadIdx.x, wid = tid >> 5, wr = wid & 1, wc = wid >> 1;
    const int m0 = blockIdx.x * 64;
    AccF acc[2][2];

    loadA<true>(dsm, Ain, m0, M, tid);           // relu(conv0)
    loadW(dsm, fch, fcl, tid);
    __syncthreads();
    mmaStage(dsm, acc, wr, wc);                  // fc
    __syncthreads();
    accToStaging(dsm, acc, wr, wc);
    __syncthreads();
    stagingToA(dsm, fcb, tid);                   // relu(fc + b)
    __syncthreads();
    loadW(dsm, f2h, f2l, tid);
    __syncthreads();
    mmaStage(dsm, acc, wr, wc);                  // fc2
    __syncthreads();
    accToStaging(dsm, acc, wr, wc);
    __syncthreads();
    stagingToA(dsm, f2b, tid);                   // relu(fc2 + b)
    __syncthreads();
    loadW(dsm, s1h, s1l, tid);
    __syncthreads();
    mmaStage(dsm, acc, wr, wc);                  // self1
    __syncthreads();
    accToStaging(dsm, acc, wr, wc);
    __syncthreads();
    stagingToGlobal<true>(dsm, b1, Cb, m0, M, tid);
    __syncthreads();
    loadW(dsm, n1h, n1l, tid);
    __syncthreads();
    mmaStage(dsm, acc, wr, wc);                  // neigh1 (A unchanged)
    __syncthreads();
    accToStaging(dsm, acc, wr, wc);
    __syncthreads();
    stagingToGlobal<false>(dsm, nullptr, Cp, m0, M, tid);
}

// K3: relu(conv1) -> packed layer2 W: cols 0-63 -> out (+b2, ld 64), cols 64-127 -> p_p (ld 64)
__global__ __launch_bounds__(256, 2)
void k3_k(const float* __restrict__ Ain,
          const __nv_bfloat16* __restrict__ l2h, const __nv_bfloat16* __restrict__ l2l,
          const float* __restrict__ b2, float* __restrict__ Co, float* __restrict__ Cp, int M)
{
    extern __shared__ char dsm[];
    const int tid = threadIdx.x, wid = tid >> 5, wr = wid & 1, wc = wid >> 1;
    const int m0 = blockIdx.x * 64;
    AccF acc[2][2];

    loadA<true>(dsm, Ain, m0, M, tid);
    loadW(dsm, l2h, l2l, tid);
    __syncthreads();
    mmaStage(dsm, acc, wr, wc);
    __syncthreads();
    accToStaging(dsm, acc, wr, wc);
    __syncthreads();
    const float* Cs = reinterpret_cast<const float*>(dsm + WOFF);
#pragma unroll
    for (int i = 0; i < 8; ++i) {
        int idx = tid + i * 256;
        int m   = idx >> 5;
        int c   = (idx & 31) * 4;
        int gm  = m0 + m;
        if (gm >= M) continue;
        float4 o = *reinterpret_cast<const float4*>(&Cs[m * CP + c]);
        if (c < 64) {
            o.x += b2[c]; o.y += b2[c + 1]; o.z += b2[c + 2]; o.w += b2[c + 3];
            *reinterpret_cast<float4*>(Co + (size_t)gm * 64 + c) = o;
        } else {
            *reinterpret_cast<float4*>(Cp + (size_t)gm * 64 + (c - 64)) = o;
        }
    }
}

// ---------------- graph kernels ----------------
__global__ void zero_k(float4* __restrict__ p, int n4) {
    int i = blockIdx.x * blockDim.x + threadIdx.x;
    if (i < n4) p[i] = make_float4(0.f, 0.f, 0.f, 0.f);
}

__global__ void deg_k(const int* __restrict__ dst) {
    int e = blockIdx.x * blockDim.x + threadIdx.x;
    if (e < NE) atomicAdd(&g_deg[dst[e]], 1.0f);
}

__global__ void inv_k() {
    int i = blockIdx.x * blockDim.x + threadIdx.x;
    if (i < NN) g_deg[i] = 1.0f / fmaxf(g_deg[i], 1.0f);
}

__device__ __forceinline__ void red4(float* p, float4 v) {
    asm volatile("red.global.add.v4.f32 [%0], {%1, %2, %3, %4};"
                 :: "l"(p), "f"(v.x), "f"(v.y), "f"(v.z), "f"(v.w) : "memory");
}

// out[dst[e]] += p[src[e]] * invdeg[dst[e]]
template<int DW>
__global__ void scatter_k(const float* __restrict__ p, const int* __restrict__ src,
                          const int* __restrict__ dst, float* __restrict__ out) {
    const int PV = DW / 4;
    int t = blockIdx.x * blockDim.x + threadIdx.x;
    int e = t / PV;
    if (e >= NE) return;
    int c = (t % PV) * 4;
    int sn = src[e];
    int dn = dst[e];
    float inv = g_deg[dn];
    float4 v = *reinterpret_cast<const float4*>(p + (size_t)sn * DW + c);
    v.x *= inv; v.y *= inv; v.z *= inv; v.w *= inv;
    red4(out + (size_t)dn * DW + c, v);
}

// ---------------- launch ----------------
extern "C" void kernel_launch(void* const* d_in, const int* in_sizes, int n_in,
                              void* d_out, int out_size) {
    const float* x        = (const float*)d_in[0];
    const int*   src      = (const int*)  d_in[1];
    const int*   dst      = (const int*)  d_in[2];
    const float* w_self0  = (const float*)d_in[3];
    const float* b_self0  = (const float*)d_in[4];
    const float* w_neigh0 = (const float*)d_in[5];
    const float* fc_w     = (const float*)d_in[6];
    const float* fc_b     = (const float*)d_in[7];
    const float* fc2_w    = (const float*)d_in[8];
    const float* fc2_b    = (const float*)d_in[9];
    const float* w_self1  = (const float*)d_in[10];
    const float* b_self1  = (const float*)d_in[11];
    const float* w_neigh1 = (const float*)d_in[12];
    const float* w_self2  = (const float*)d_in[13];
    const float* b_self2  = (const float*)d_in[14];
    const float* w_neigh2 = (const float*)d_in[15];
    float* out = (float*)d_out;

    float *p_a, *p_b, *p_p, *p_deg;
    __nv_bfloat16* p_wb;
    cudaGetSymbolAddress((void**)&p_a,   g_a);
    cudaGetSymbolAddress((void**)&p_b,   g_b);
    cudaGetSymbolAddress((void**)&p_p,   g_p);
    cudaGetSymbolAddress((void**)&p_deg, g_deg);
    cudaGetSymbolAddress((void**)&p_wb,  g_wb);

    const __nv_bfloat16 *s0h = p_wb,          *s0l = p_wb + 16384;
    const __nv_bfloat16 *n0h = p_wb + 32768,  *n0l = p_wb + 49152;
    const __nv_bfloat16 *fch = p_wb + 65536,  *fcl = p_wb + 81920;
    const __nv_bfloat16 *f2h = p_wb + 98304,  *f2l = p_wb + 114688;
    const __nv_bfloat16 *s1h = p_wb + 131072, *s1l = p_wb + 147456;
    const __nv_bfloat16 *n1h = p_wb + 163840, *n1l = p_wb + 180224;
    const __nv_bfloat16 *l2h = p_wb + 196608, *l2l = p_wb + 212992;

    cudaFuncSetAttribute(k1_k, cudaFuncAttributeMaxDynamicSharedMemorySize, SMEMB);
    cudaFuncSetAttribute(k2_k, cudaFuncAttributeMaxDynamicSharedMemorySize, SMEMB);
    cudaFuncSetAttribute(k3_k, cudaFuncAttributeMaxDynamicSharedMemorySize, SMEMB);

    const int GB = (NN + 63) / 64;   // 1563
    const int T  = 256;

    // ---- prep: degrees -> inverse, weight preconversion ----
    zero_k<<<(NN / 4 + T - 1) / T, T>>>((float4*)p_deg, NN / 4);
    deg_k<<<(NE + T - 1) / T, T>>>(dst);
    inv_k<<<(NN + T - 1) / T, T>>>();
    WSrc ws; ws.s[0] = w_self0; ws.s[1] = w_neigh0; ws.s[2] = fc_w; ws.s[3] = fc2_w;
             ws.s[4] = w_self1; ws.s[5] = w_neigh1; ws.s[6] = w_self2; ws.s[7] = w_neigh2;
    wconv_k<<<(114688 + T - 1) / T, T>>>(ws);

    // ---- layer 0 ----
    k1_k<<<GB, T, SMEMB>>>(x, s0h, s0l, n0h, n0l, b_self0, p_a, p_p, NN);
    scatter_k<128><<<(NE * 32 + T - 1) / T, T>>>(p_p, src, dst, p_a);   // p_a = conv0 (pre-relu)

    // ---- fc / fc2 / layer 1 ----
    k2_k<<<GB, T, SMEMB>>>(p_a, fch, fcl, fc_b, f2h, f2l, fc2_b,
                           s1h, s1l, b_self1, n1h, n1l, p_b, p_p, NN);
    scatter_k<128><<<(NE * 32 + T - 1) / T, T>>>(p_p, src, dst, p_b);   // p_b = conv1 (pre-relu)

    // ---- layer 2 ----
    k3_k<<<GB, T, SMEMB>>>(p_b, l2h, l2l, b_self2, out, p_p, NN);
    scatter_k<64><<<(NE * 16 + T - 1) / T, T>>>(p_p, src, dst, out);
}

// round 8
// speedup vs baseline: 1.6145x; 1.1633x over previous
#include <cuda_runtime.h>
#include <cuda_bf16.h>
#include <mma.h>
#include <cstdint>

using namespace nvcuda;

#define NN 100000
#define NE 600000

// ---------------- scratch (device globals; no allocation allowed) ----------------
__device__ float g_a  [(size_t)NN * 128];
__device__ float g_b  [(size_t)NN * 128];
__device__ float g_p  [(size_t)NN * 128];
__device__ __nv_bfloat16 g_wb[229376];   // 7 weight blocks (layer2 pair packed), transposed, hi+lo
// CSR build
__device__ int g_cnt   [NN];
__device__ int g_rowtmp[NN];
__device__ int g_rowptr[NN + 1];
__device__ int g_cur   [NN];
__device__ int g_bsum  [256];
__device__ int g_eid   [NE];

// smem layout (bytes): Ahi@0, Alo@17408, Whi@34816, Wlo@69632 -> total 104448
#define PP    136
#define ASZ   17408
#define WOFF  34816
#define SMEMB 104448
#define CP    132

__device__ __forceinline__ void split2(float a, float b, uint32_t& hi, uint32_t& lo) {
    __nv_bfloat16 ha = __float2bfloat16(a), hb = __float2bfloat16(b);
    float ra = a - __bfloat162float(ha), rb = b - __bfloat162float(hb);
    __nv_bfloat16 la = __float2bfloat16(ra), lb = __float2bfloat16(rb);
    hi = ((uint32_t)__bfloat16_as_ushort(hb) << 16) | (uint32_t)__bfloat16_as_ushort(ha);
    lo = ((uint32_t)__bfloat16_as_ushort(lb) << 16) | (uint32_t)__bfloat16_as_ushort(la);
}

// ---------------- weight conversion (unchanged from R7) ----------------
struct WSrc { const float* s[8]; };

__global__ void wconv_k(WSrc ws) {
    int idx = blockIdx.x * blockDim.x + threadIdx.x;
    if (idx >= 114688) return;
    int m, r, ncols;
    if (idx < 98304) { m = idx >> 14; r = idx & 16383; ncols = 128; }
    else             { m = 6 + ((idx - 98304) >> 13); r = (idx - 98304) & 8191; ncols = 64; }
    int k = r / ncols, n = r % ncols;
    float v = ws.s[m][r];
    __nv_bfloat16 h = __float2bfloat16(v);
    __nv_bfloat16 l = __float2bfloat16(v - __bfloat162float(h));
    int base, nc;
    if (m < 6)      { const int offs[6] = {0, 32768, 65536, 98304, 131072, 163840};
                      base = offs[m]; nc = n; }
    else if (m == 6){ base = 196608; nc = n; }
    else            { base = 196608; nc = 64 + n; }
    g_wb[base + nc * 128 + k]         = h;
    g_wb[base + 16384 + nc * 128 + k] = l;
}

// ================= CSR build =================
__global__ void czero_k() {
    int i = blockIdx.x * blockDim.x + threadIdx.x;
    if (i < NN) g_cnt[i] = 0;
}
__global__ void hist_k(const int* __restrict__ dst) {
    int e = blockIdx.x * blockDim.x + threadIdx.x;
    if (e < NE) atomicAdd(&g_cnt[dst[e]], 1);
}
// block-level inclusive scan (512 threads), write per-block totals
__global__ void scan1_k() {
    __shared__ int sm[512];
    int i = blockIdx.x * 512 + threadIdx.x;
    int v = (i < NN) ? g_cnt[i] : 0;
    sm[threadIdx.x] = v;
    __syncthreads();
#pragma unroll
    for (int off = 1; off < 512; off <<= 1) {
        int t = (threadIdx.x >= off) ? sm[threadIdx.x - off] : 0;
        __syncthreads();
        sm[threadIdx.x] += t;
        __syncthreads();
    }
    if (i < NN) g_rowtmp[i] = sm[threadIdx.x];
    if (threadIdx.x == 511) g_bsum[blockIdx.x] = sm[511];
}
// exclusive scan of 196 block sums (one 256-thread block)
__global__ void scan2_k() {
    __shared__ int sm[256];
    int v = (threadIdx.x < 196) ? g_bsum[threadIdx.x] : 0;
    sm[threadIdx.x] = v;
    __syncthreads();
#pragma unroll
    for (int off = 1; off < 256; off <<= 1) {
        int t = (threadIdx.x >= off) ? sm[threadIdx.x - off] : 0;
        __syncthreads();
        sm[threadIdx.x] += t;
        __syncthreads();
    }
    if (threadIdx.x < 196) g_bsum[threadIdx.x] = (threadIdx.x == 0) ? 0 : sm[threadIdx.x - 1];
}
// rowptr (exclusive) + cursor init
__global__ void scan3_k() {
    int i = blockIdx.x * 512 + threadIdx.x;
    if (i < NN) {
        int rp = g_rowtmp[i] - g_cnt[i] + g_bsum[blockIdx.x];
        g_rowptr[i] = rp;
        g_cur[i]    = rp;
    }
    if (i == 0) g_rowptr[NN] = NE;
}
__global__ void fill_k(const int* __restrict__ src, const int* __restrict__ dst) {
    int e = blockIdx.x * blockDim.x + threadIdx.x;
    if (e >= NE) return;
    int pos = atomicAdd(&g_cur[dst[e]], 1);
    g_eid[pos] = src[e];
}

// ================= gather aggregation: warp per node, pull model =================
// out[n] += (1/max(deg,1)) * sum_{s in N(n)} p[s]     (out holds self term + bias)
__global__ __launch_bounds__(256)
void gath128_k(const float* __restrict__ p, float* __restrict__ out) {
    int w    = (blockIdx.x * 256 + threadIdx.x) >> 5;
    int lane = threadIdx.x & 31;
    if (w >= NN) return;
    int beg = g_rowptr[w], end = g_rowptr[w + 1];
    float4 acc = make_float4(0.f, 0.f, 0.f, 0.f);
    int e = beg;
    for (; e + 1 < end; e += 2) {
        int s0 = g_eid[e], s1 = g_eid[e + 1];
        float4 v0 = *reinterpret_cast<const float4*>(p + (size_t)s0 * 128 + lane * 4);
        float4 v1 = *reinterpret_cast<const float4*>(p + (size_t)s1 * 128 + lane * 4);
        acc.x += v0.x + v1.x; acc.y += v0.y + v1.y;
        acc.z += v0.z + v1.z; acc.w += v0.w + v1.w;
    }
    if (e < end) {
        int s0 = g_eid[e];
        float4 v0 = *reinterpret_cast<const float4*>(p + (size_t)s0 * 128 + lane * 4);
        acc.x += v0.x; acc.y += v0.y; acc.z += v0.z; acc.w += v0.w;
    }
    float inv = 1.0f / fmaxf((float)(end - beg), 1.0f);
    float4 o = *reinterpret_cast<const float4*>(out + (size_t)w * 128 + lane * 4);
    o.x += acc.x * inv; o.y += acc.y * inv; o.z += acc.z * inv; o.w += acc.w * inv;
    *reinterpret_cast<float4*>(out + (size_t)w * 128 + lane * 4) = o;
}

__global__ __launch_bounds__(256)
void gath64_k(const float* __restrict__ p, float* __restrict__ out) {
    int w    = (blockIdx.x * 256 + threadIdx.x) >> 5;
    int lane = threadIdx.x & 31;
    if (w >= NN) return;
    int beg = g_rowptr[w], end = g_rowptr[w + 1];
    float2 acc = make_float2(0.f, 0.f);
    int e = beg;
    for (; e + 1 < end; e += 2) {
        int s0 = g_eid[e], s1 = g_eid[e + 1];
        float2 v0 = *reinterpret_cast<const float2*>(p + (size_t)s0 * 64 + lane * 2);
        float2 v1 = *reinterpret_cast<const float2*>(p + (size_t)s1 * 64 + lane * 2);
        acc.x += v0.x + v1.x; acc.y += v0.y + v1.y;
    }
    if (e < end) {
        int s0 = g_eid[e];
        float2 v0 = *reinterpret_cast<const float2*>(p + (size_t)s0 * 64 + lane * 2);
        acc.x += v0.x; acc.y += v0.y;
    }
    float inv = 1.0f / fmaxf((float)(end - beg), 1.0f);
    float2 o = *reinterpret_cast<const float2*>(out + (size_t)w * 64 + lane * 2);
    o.x += acc.x * inv; o.y += acc.y * inv;
    *reinterpret_cast<float2*>(out + (size_t)w * 64 + lane * 2) = o;
}

// ================= GEMM building blocks (unchanged from R7) =================
template<bool RELU>
__device__ __forceinline__ void loadA(char* dsm, const float* __restrict__ A, int m0, int M, int tid) {
    __nv_bfloat16* Ahi = reinterpret_cast<__nv_bfloat16*>(dsm);
    __nv_bfloat16* Alo = reinterpret_cast<__nv_bfloat16*>(dsm + ASZ);
#pragma unroll
    for (int i = 0; i < 8; ++i) {
        int idx = tid + i * 256;
        int m   = idx >> 5;
        int k0  = (idx & 31) * 4;
        float4 v = make_float4(0.f, 0.f, 0.f, 0.f);
        int gm = m0 + m;
        if (gm < M) v = *reinterpret_cast<const float4*>(A + (size_t)gm * 128 + k0);
        if (RELU) { v.x = fmaxf(v.x, 0.f); v.y = fmaxf(v.y, 0.f); v.z = fmaxf(v.z, 0.f); v.w = fmaxf(v.w, 0.f); }
        uint32_t h0, l0, h1, l1;
        split2(v.x, v.y, h0, l0);
        split2(v.z, v.w, h1, l1);
        *reinterpret_cast<uint2*>(&Ahi[m * PP + k0]) = make_uint2(h0, h1);
        *reinterpret_cast<uint2*>(&Alo[m * PP + k0]) = make_uint2(l0, l1);
    }
}

__device__ __forceinline__ void loadW(char* dsm, const __nv_bfloat16* __restrict__ whi,
                                      const __nv_bfloat16* __restrict__ wlo, int tid) {
    __nv_bfloat16* Whi = reinterpret_cast<__nv_bfloat16*>(dsm + WOFF);
    __nv_bfloat16* Wlo = reinterpret_cast<__nv_bfloat16*>(dsm + WOFF + ASZ * 2);
#pragma unroll
    for (int i = 0; i < 16; ++i) {
        int idx  = tid + i * 256;
        int half = idx >> 11;
        int r    = idx & 2047;
        int n    = r >> 4;
        int c    = r & 15;
        const uint4* srcp = reinterpret_cast<const uint4*>(half ? wlo : whi);
        __nv_bfloat16* dp = half ? Wlo : Whi;
        *reinterpret_cast<uint4*>(reinterpret_cast<char*>(&dp[n * PP]) + c * 16) = srcp[n * 16 + c];
    }
}

typedef wmma::fragment<wmma::accumulator, 16, 16, 16, float> AccF;

__device__ __forceinline__ void mmaStage(char* dsm, AccF acc[2][2], int wr, int wc) {
    __nv_bfloat16* Ahi = reinterpret_cast<__nv_bfloat16*>(dsm);
    __nv_bfloat16* Alo = reinterpret_cast<__nv_bfloat16*>(dsm + ASZ);
    __nv_bfloat16* Whi = reinterpret_cast<__nv_bfloat16*>(dsm + WOFF);
    __nv_bfloat16* Wlo = reinterpret_cast<__nv_bfloat16*>(dsm + WOFF + ASZ * 2);
#pragma unroll
    for (int i = 0; i < 2; ++i)
#pragma unroll
        for (int j = 0; j < 2; ++j) wmma::fill_fragment(acc[i][j], 0.0f);
#pragma unroll
    for (int ks = 0; ks < 8; ++ks) {
        const int k = ks * 16;
        wmma::fragment<wmma::matrix_a, 16, 16, 16, __nv_bfloat16, wmma::row_major> ah[2], al[2];
        wmma::fragment<wmma::matrix_b, 16, 16, 16, __nv_bfloat16, wmma::col_major> bh[2], bl[2];
#pragma unroll
        for (int i = 0; i < 2; ++i) {
            int m = wr * 32 + i * 16;
            wmma::load_matrix_sync(ah[i], &Ahi[m * PP + k], PP);
            wmma::load_matrix_sync(al[i], &Alo[m * PP + k], PP);
        }
#pragma unroll
        for (int j = 0; j < 2; ++j) {
            int n = wc * 32 + j * 16;
            wmma::load_matrix_sync(bh[j], &Whi[n * PP + k], PP);
            wmma::load_matrix_sync(bl[j], &Wlo[n * PP + k], PP);
        }
#pragma unroll
        for (int i = 0; i < 2; ++i)
#pragma unroll
            for (int j = 0; j < 2; ++j) {
                wmma::mma_sync(acc[i][j], ah[i], bh[j], acc[i][j]);
                wmma::mma_sync(acc[i][j], ah[i], bl[j], acc[i][j]);
                wmma::mma_sync(acc[i][j], al[i], bh[j], acc[i][j]);
            }
    }
}

__device__ __forceinline__ void accToStaging(char* dsm, AccF acc[2][2], int wr, int wc) {
    float* Cs = reinterpret_cast<float*>(dsm + WOFF);
#pragma unroll
    for (int i = 0; i < 2; ++i)
#pragma unroll
        for (int j = 0; j < 2; ++j)
            wmma::store_matrix_sync(&Cs[(wr * 32 + i * 16) * CP + wc * 32 + j * 16], acc[i][j], CP, wmma::mem_row_major);
}

__device__ __forceinline__ void stagingToA(char* dsm, const float* __restrict__ bias, int tid) {
    const float* Cs = reinterpret_cast<const float*>(dsm + WOFF);
    __nv_bfloat16* Ahi = reinterpret_cast<__nv_bfloat16*>(dsm);
    __nv_bfloat16* Alo = reinterpret_cast<__nv_bfloat16*>(dsm + ASZ);
#pragma unroll
    for (int i = 0; i < 8; ++i) {
        int idx = tid + i * 256;
        int m   = idx >> 5;
        int c   = (idx & 31) * 4;
        float4 v = *reinterpret_cast<const float4*>(&Cs[m * CP + c]);
        v.x = fmaxf(v.x + bias[c + 0], 0.f);
        v.y = fmaxf(v.y + bias[c + 1], 0.f);
        v.z = fmaxf(v.z + bias[c + 2], 0.f);
        v.w = fmaxf(v.w + bias[c + 3], 0.f);
        uint32_t h0, l0, h1, l1;
        split2(v.x, v.y, h0, l0);
        split2(v.z, v.w, h1, l1);
        *reinterpret_cast<uint2*>(&Ahi[m * PP + c]) = make_uint2(h0, h1);
        *reinterpret_cast<uint2*>(&Alo[m * PP + c]) = make_uint2(l0, l1);
    }
}

template<bool BIAS>
__device__ __forceinline__ void stagingToGlobal(char* dsm, const float* __restrict__ bias,
                                                float* __restrict__ C, int m0, int M, int tid) {
    const float* Cs = reinterpret_cast<const float*>(dsm + WOFF);
#pragma unroll
    for (int i = 0; i < 8; ++i) {
        int idx = tid + i * 256;
        int m   = idx >> 5;
        int c   = (idx & 31) * 4;
        int gm  = m0 + m;
        if (gm >= M) continue;
        float4 o = *reinterpret_cast<const float4*>(&Cs[m * CP + c]);
        if (BIAS) { o.x += bias[c]; o.y += bias[c + 1]; o.z += bias[c + 2]; o.w += bias[c + 3]; }
        *reinterpret_cast<float4*>(C + (size_t)gm * 128 + c) = o;
    }
}

// ================= fused kernels (unchanged from R7) =================
__global__ __launch_bounds__(256, 2)
void k1_k(const float* __restrict__ x,
          const __nv_bfloat16* __restrict__ s0h, const __nv_bfloat16* __restrict__ s0l,
          const __nv_bfloat16* __restrict__ n0h, const __nv_bfloat16* __restrict__ n0l,
          const float* __restrict__ b0, float* __restrict__ Ca, float* __restrict__ Cp, int M)
{
    extern __shared__ char dsm[];
    const int tid = threadIdx.x, wid = tid >> 5, wr = wid & 1, wc = wid >> 1;
    const int m0 = blockIdx.x * 64;
    AccF acc[2][2];

    loadA<false>(dsm, x, m0, M, tid);
    loadW(dsm, s0h, s0l, tid);
    __syncthreads();
    mmaStage(dsm, acc, wr, wc);
    __syncthreads();
    accToStaging(dsm, acc, wr, wc);
    __syncthreads();
    stagingToGlobal<true>(dsm, b0, Ca, m0, M, tid);
    __syncthreads();
    loadW(dsm, n0h, n0l, tid);
    __syncthreads();
    mmaStage(dsm, acc, wr, wc);
    __syncthreads();
    accToStaging(dsm, acc, wr, wc);
    __syncthreads();
    stagingToGlobal<false>(dsm, nullptr, Cp, m0, M, tid);
}

__global__ __launch_bounds__(256, 2)
void k2_k(const float* __restrict__ Ain,
          const __nv_bfloat16* __restrict__ fch, const __nv_bfloat16* __restrict__ fcl, const float* __restrict__ fcb,
          const __nv_bfloat16* __restrict__ f2h, const __nv_bfloat16* __restrict__ f2l, const float* __restrict__ f2b,
          const __nv_bfloat16* __restrict__ s1h, const __nv_bfloat16* __restrict__ s1l, const float* __restrict__ b1,
          const __nv_bfloat16* __restrict__ n1h, const __nv_bfloat16* __restrict__ n1l,
          float* __restrict__ Cb, float* __restrict__ Cp, int M)
{
    extern __shared__ char dsm[];
    const int tid = threadIdx.x, wid = tid >> 5, wr = wid & 1, wc = wid >> 1;
    const int m0 = blockIdx.x * 64;
    AccF acc[2][2];

    loadA<true>(dsm, Ain, m0, M, tid);
    loadW(dsm, fch, fcl, tid);
    __syncthreads();
    mmaStage(dsm, acc, wr, wc);
    __syncthreads();
    accToStaging(dsm, acc, wr, wc);
    __syncthreads();
    stagingToA(dsm, fcb, tid);
    __syncthreads();
    loadW(dsm, f2h, f2l, tid);
    __syncthreads();
    mmaStage(dsm, acc, wr, wc);
    __syncthreads();
    accToStaging(dsm, acc, wr, wc);
    __syncthreads();
    stagingToA(dsm, f2b, tid);
    __syncthreads();
    loadW(dsm, s1h, s1l, tid);
    __syncthreads();
    mmaStage(dsm, acc, wr, wc);
    __syncthreads();
    accToStaging(dsm, acc, wr, wc);
    __syncthreads();
    stagingToGlobal<true>(dsm, b1, Cb, m0, M, tid);
    __syncthreads();
    loadW(dsm, n1h, n1l, tid);
    __syncthreads();
    mmaStage(dsm, acc, wr, wc);
    __syncthreads();
    accToStaging(dsm, acc, wr, wc);
    __syncthreads();
    stagingToGlobal<false>(dsm, nullptr, Cp, m0, M, tid);
}

__global__ __launch_bounds__(256, 2)
void k3_k(const float* __restrict__ Ain,
          const __nv_bfloat16* __restrict__ l2h, const __nv_bfloat16* __restrict__ l2l,
          const float* __restrict__ b2, float* __restrict__ Co, float* __restrict__ Cp, int M)
{
    extern __shared__ char dsm[];
    const int tid = threadIdx.x, wid = tid >> 5, wr = wid & 1, wc = wid >> 1;
    const int m0 = blockIdx.x * 64;
    AccF acc[2][2];

    loadA<true>(dsm, Ain, m0, M, tid);
    loadW(dsm, l2h, l2l, tid);
    __syncthreads();
    mmaStage(dsm, acc, wr, wc);
    __syncthreads();
    accToStaging(dsm, acc, wr, wc);
    __syncthreads();
    const float* Cs = reinterpret_cast<const float*>(dsm + WOFF);
#pragma unroll
    for (int i = 0; i < 8; ++i) {
        int idx = tid + i * 256;
        int m   = idx >> 5;
        int c   = (idx & 31) * 4;
        int gm  = m0 + m;
        if (gm >= M) continue;
        float4 o = *reinterpret_cast<const float4*>(&Cs[m * CP + c]);
        if (c < 64) {
            o.x += b2[c]; o.y += b2[c + 1]; o.z += b2[c + 2]; o.w += b2[c + 3];
            *reinterpret_cast<float4*>(Co + (size_t)gm * 64 + c) = o;
        } else {
            *reinterpret_cast<float4*>(Cp + (size_t)gm * 64 + (c - 64)) = o;
        }
    }
}

// ---------------- launch ----------------
extern "C" void kernel_launch(void* const* d_in, const int* in_sizes, int n_in,
                              void* d_out, int out_size) {
    const float* x        = (const float*)d_in[0];
    const int*   src      = (const int*)  d_in[1];
    const int*   dst      = (const int*)  d_in[2];
    const float* w_self0  = (const float*)d_in[3];
    const float* b_self0  = (const float*)d_in[4];
    const float* w_neigh0 = (const float*)d_in[5];
    const float* fc_w     = (const float*)d_in[6];
    const float* fc_b     = (const float*)d_in[7];
    const float* fc2_w    = (const float*)d_in[8];
    const float* fc2_b    = (const float*)d_in[9];
    const float* w_self1  = (const float*)d_in[10];
    const float* b_self1  = (const float*)d_in[11];
    const float* w_neigh1 = (const float*)d_in[12];
    const float* w_self2  = (const float*)d_in[13];
    const float* b_self2  = (const float*)d_in[14];
    const float* w_neigh2 = (const float*)d_in[15];
    float* out = (float*)d_out;

    float *p_a, *p_b, *p_p;
    __nv_bfloat16* p_wb;
    cudaGetSymbolAddress((void**)&p_a,  g_a);
    cudaGetSymbolAddress((void**)&p_b,  g_b);
    cudaGetSymbolAddress((void**)&p_p,  g_p);
    cudaGetSymbolAddress((void**)&p_wb, g_wb);

    const __nv_bfloat16 *s0h = p_wb,          *s0l = p_wb + 16384;
    const __nv_bfloat16 *n0h = p_wb + 32768,  *n0l = p_wb + 49152;
    const __nv_bfloat16 *fch = p_wb + 65536,  *fcl = p_wb + 81920;
    const __nv_bfloat16 *f2h = p_wb + 98304,  *f2l = p_wb + 114688;
    const __nv_bfloat16 *s1h = p_wb + 131072, *s1l = p_wb + 147456;
    const __nv_bfloat16 *n1h = p_wb + 163840, *n1l = p_wb + 180224;
    const __nv_bfloat16 *l2h = p_wb + 196608, *l2l = p_wb + 212992;

    cudaFuncSetAttribute(k1_k, cudaFuncAttributeMaxDynamicSharedMemorySize, SMEMB);
    cudaFuncSetAttribute(k2_k, cudaFuncAttributeMaxDynamicSharedMemorySize, SMEMB);
    cudaFuncSetAttribute(k3_k, cudaFuncAttributeMaxDynamicSharedMemorySize, SMEMB);

    const int GB = (NN + 63) / 64;   // 1563
    const int T  = 256;
    const int GW = (NN * 32 + T - 1) / T;   // warp-per-node grids

    // ---- prep: CSR build + weight preconversion ----
    czero_k<<<(NN + T - 1) / T, T>>>();
    hist_k<<<(NE + T - 1) / T, T>>>(dst);
    scan1_k<<<196, 512>>>();
    scan2_k<<<1, 256>>>();
    scan3_k<<<196, 512>>>();
    fill_k<<<(NE + T - 1) / T, T>>>(src, dst);
    WSrc ws; ws.s[0] = w_self0; ws.s[1] = w_neigh0; ws.s[2] = fc_w; ws.s[3] = fc2_w;
             ws.s[4] = w_self1; ws.s[5] = w_neigh1; ws.s[6] = w_self2; ws.s[7] = w_neigh2;
    wconv_k<<<(114688 + T - 1) / T, T>>>(ws);

    // ---- layer 0 ----
    k1_k<<<GB, T, SMEMB>>>(x, s0h, s0l, n0h, n0l, b_self0, p_a, p_p, NN);
    gath128_k<<<GW, T>>>(p_p, p_a);                                     // p_a = conv0 (pre-relu)

    // ---- fc / fc2 / layer 1 ----
    k2_k<<<GB, T, SMEMB>>>(p_a, fch, fcl, fc_b, f2h, f2l, fc2_b,
                           s1h, s1l, b_self1, n1h, n1l, p_b, p_p, NN);
    gath128_k<<<GW, T>>>(p_p, p_b);                                     // p_b = conv1 (pre-relu)

    // ---- layer 2 ----
    k3_k<<<GB, T, SMEMB>>>(p_b, l2h, l2l, b_self2, out, p_p, NN);
    gath64_k<<<GW, T>>>(p_p, out);
}